// round 15
// baseline (speedup 1.0000x reference)
#include <cuda_runtime.h>

// Apply 2x2 complex gate (rows r0, r1 as (re0,im0,re1,im1)) to REAL 2-vec (c,s).
__device__ __forceinline__ float4 mat_real(float4 r0, float4 r1, float c, float s) {
    return make_float4(r0.x * c + r0.z * s, r0.y * c + r0.w * s,
                       r1.x * c + r1.z * s, r1.y * c + r1.w * s);
}
// Same for complex 2-vec v = (v0r,v0i,v1r,v1i).
__device__ __forceinline__ float4 mat_cpx(float4 r0, float4 r1, float4 v) {
    return make_float4(r0.x * v.x - r0.y * v.y + r0.z * v.z - r0.w * v.w,
                       r0.x * v.y + r0.y * v.x + r0.z * v.w + r0.w * v.z,
                       r1.x * v.x - r1.y * v.y + r1.z * v.z - r1.w * v.w,
                       r1.x * v.y + r1.y * v.x + r1.z * v.w + r1.w * v.z);
}
__device__ __forceinline__ float dz(float4 v) {        // |w0|^2 - |w1|^2
    return v.x * v.x + v.y * v.y - v.z * v.z - v.w * v.w;
}
__device__ __forceinline__ float p1_real(float4 r1, float c, float s) {
    float tr = r1.x * c + r1.z * s, ti = r1.y * c + r1.w * s;
    return tr * tr + ti * ti;
}

// Warp-autonomous classical-branching evaluation (D=diag(1,i) basis; initial
// per-qubit vector REAL (sin pi p, -cos pi p); fused pair gate
// U' = G(tx)*diag(e^-ia, e^ia)).
// One warp = 8 w-positions x 4 channels of ONE output row. Each lane produces
// one trig pixel of the warp's private 3x10 window + one gate-table entry,
// __syncwarp, then finishes one sim. NO block barrier anywhere.
__global__ void __launch_bounds__(256)
quanv_kernel(const float* __restrict__ x, const float* __restrict__ qp,
             float* __restrict__ out) {
    __shared__ float2 sT[8][32];       // per-warp trig window (3 rows x 10 cols)
    __shared__ float4 sU[8][4][17];    // per-warp gate table, padded stride
                                       // (272B/ch -> conflict-free LDS.128)

    int tid = threadIdx.x;
    int l = tid & 31, wp = tid >> 5;
    int blk = blockIdx.x;              // = b*15 + rb ; rows h = 2rb, 2rb+1
    int rb = blk % 15, b = blk / 15;
    int h = 2 * rb + (wp >> 2);        // warp's output row
    int w0 = 8 * (wp & 3);             // warp's first w position
    int ch = l & 3, wl = l >> 2, w = w0 + wl;

    // --- gate-table entry: lane -> (ch_g, k) ---
    {
        int cg = l >> 3, k = l & 7;
        float tz = qp[cg * 16 + 2 * k], tx = qp[cg * 16 + 2 * k + 1];
        float sa, ca, sx, cx;
        __sincosf(0.5f * tz, &sa, &ca);
        __sincosf(0.5f * tx, &sx, &cx);
        sU[wp][cg][2 * k]     = make_float4(cx * ca, -cx * sa, -sx * ca, -sx * sa);
        sU[wp][cg][2 * k + 1] = make_float4(sx * ca, -sx * sa,  cx * ca,  cx * sa);
    }
    // --- trig pixel: lanes 0..29 -> window (rr = l/10, cc = l%10) ---
    if (l < 30) {
        int rr = l / 10, cc = l % 10;
        int pr = min(29, max(0, h - 1 + rr));
        int pc = min(29, max(0, w0 - 1 + cc));
        const float* px = x + ((b * 30 + pr) * 30 + pc) * 3;
        float p = (px[0] + px[1] + px[2]) * (1.0f / 3.0f);
        float s, c;
        __sincosf(3.14159265358979f * p, &s, &c);
        sT[wp][l] = make_float2(s, -c);    // index = rr*10 + cc
    }
    __syncwarp();

    if (w >= 30) return;                   // tail lanes of the w0=24 warp
    int oidx = ((b * 30 + h) * 30 + w) * 4 + ch;
    if (h == 0 || h == 29 || w == 0 || w == 29) {
        out[oidx] = 0.0f;                  // padded border
        return;
    }

    const float4* gu = sU[wp][ch];
    const float2* tr2 = sT[wp];
    // qubit q = dr*3+dc -> tr2[dr*10 + wl + dc]
    float2 q0 = tr2[wl],      q1 = tr2[wl + 1],  q2 = tr2[wl + 2];
    float2 q3 = tr2[10 + wl], q4 = tr2[11 + wl], q5 = tr2[12 + wl];
    float2 q6 = tr2[20 + wl], q7 = tr2[21 + wl], q8 = tr2[22 + wl];

    // ---------- B side: nB1 = P(q4 = 1) ----------
    float p8 = q8.y * q8.y;
    float t7 = p1_real(gu[7], q7.x, q7.y);            // U3 row1 (pair k=3)
    float P7 = (1.0f - p8) * (q7.y * q7.y) + p8 * t7;
    float t6 = p1_real(gu[11], q6.x, q6.y);           // U5 row1 (pair k=5)
    float P6 = (1.0f - P7) * (q6.y * q6.y) + P7 * t6;
    float p5 = q5.y * q5.y;

    float4 m10 = mat_real(gu[8], gu[9], q4.x, q4.y);  // U4 * v4 (pair k=4)
    float n00 = q4.y * q4.y;
    float n10 = m10.z * m10.z + m10.w * m10.w;
    float n01 = p1_real(gu[13], q4.x, q4.y);          // |row1(U6) v4|^2
    float4 r6 = gu[13];
    float tr = r6.x * m10.x - r6.y * m10.y + r6.z * m10.z - r6.w * m10.w;
    float ti = r6.x * m10.y + r6.y * m10.x + r6.z * m10.w + r6.w * m10.z;
    float n11 = tr * tr + ti * ti;
    float nB1 = (1.0f - p5) * ((1.0f - P6) * n00 + P6 * n01)
              + p5 * ((1.0f - P6) * n10 + P6 * n11);

    // ---------- A side: branch probs for q1, q2 ----------
    float p1p = q1.y * q1.y;
    float p3 = q3.y * q3.y;
    float t2 = p1_real(gu[3], q2.x, q2.y);            // U1 row1 (pair k=1)
    float P2 = (1.0f - p3) * (q2.y * q2.y) + p3 * t2;

    // ---------- q0 chain: U0^{b1}, U2^{b2}, U7^{b4} ----------
    float4 v10 = mat_real(gu[0], gu[1], q0.x, q0.y);
    float4 v01 = mat_real(gu[4], gu[5], q0.x, q0.y);
    float4 v11 = mat_cpx(gu[4], gu[5], v10);
    float4 w00 = mat_real(gu[14], gu[15], q0.x, q0.y);
    float4 w10 = mat_cpx(gu[14], gu[15], v10);
    float4 w01 = mat_cpx(gu[14], gu[15], v01);
    float4 w11 = mat_cpx(gu[14], gu[15], v11);

    float d00 = q0.x * q0.x - q0.y * q0.y;
    float nB0 = 1.0f - nB1;
    float e00 = nB0 * d00 + nB1 * dz(w00);
    float e10 = nB0 * dz(v10) + nB1 * dz(w10);
    float e01 = nB0 * dz(v01) + nB1 * dz(w01);
    float e11 = nB0 * dz(v11) + nB1 * dz(w11);

    float z = (1.0f - p1p) * ((1.0f - P2) * e00 + P2 * e01)
            + p1p * ((1.0f - P2) * e10 + P2 * e11);

    out[oidx] = 0.5f * (z + 1.0f);
}

extern "C" void kernel_launch(void* const* d_in, const int* in_sizes, int n_in,
                              void* d_out, int out_size) {
    const float* x = (const float*)d_in[0];       // (8,30,30,3) float32
    const float* qp = (const float*)d_in[1];      // (4,16) float32
    float* out = (float*)d_out;                   // (8,30,30,4) float32

    quanv_kernel<<<120, 256>>>(x, qp, out);       // 8 autonomous warps/block
}